// round 13
// baseline (speedup 1.0000x reference)
#include <cuda_runtime.h>

#define Bb   8
#define Nn   8192
#define Mm   2048
#define Cc   64
#define CTt  64
#define KNN  32
#define TILE 512
#define SP2  68    // floats per staged row-half; 272B, 16B-aligned

// Scratch (__device__ globals; cudaMalloc is forbidden)
// g_comb row n: [feat c0..63 | temb c0..63]
__device__ float  g_comb[(size_t)Bb * Nn * 128];   // 32 MB (L2-resident)
__device__ float4 g_xyz[(size_t)Bb * Nn];          //  4 MB  (x,y,z,|p|^2)

__device__ __forceinline__ void cp16(void* sdst, const void* gsrc) {
    unsigned sa = (unsigned)__cvta_generic_to_shared(sdst);
    asm volatile("cp.async.cg.shared.global [%0], [%1], 16;"
                 :: "r"(sa), "l"(gsrc));
}
#define CP_COMMIT() asm volatile("cp.async.commit_group;")
#define CP_WAIT1()  asm volatile("cp.async.wait_group 1;")
#define CP_WAIT0()  asm volatile("cp.async.wait_group 0;")

// ---------------------------------------------------------------------------
// Prep: transpose [B][C][N] -> combined [B][N][128], plus xyz packing.
// ---------------------------------------------------------------------------
__global__ void prep_kernel(const float* __restrict__ feat,
                            const float* __restrict__ temb,
                            const float* __restrict__ pts)
{
    __shared__ float tile[32][33];
    int zz    = blockIdx.z;
    int b     = zz >> 1;
    int which = zz & 1;
    const float* src = which ? temb : feat;
    int cbase        = which ? 64 : 0;

    int n0 = blockIdx.x * 32;
    int c0 = blockIdx.y * 32;
    int j  = threadIdx.x;                     // 0..7
    int i  = threadIdx.y;                     // 0..31
    int t  = i * 8 + j;

    const float* s = src + (size_t)b * Cc * Nn;
    float*       d = g_comb + (size_t)b * Nn * 128;

    float4 v = __ldcs((const float4*)(s + (size_t)(c0 + i) * Nn + n0 + 4 * j));
    tile[i][4 * j + 0] = v.x;
    tile[i][4 * j + 1] = v.y;
    tile[i][4 * j + 2] = v.z;
    tile[i][4 * j + 3] = v.w;

    if (which == 0 && blockIdx.y == 0 && t < 32) {
        int n = n0 + t;
        const float* p = pts + (size_t)b * 3 * Nn;
        float x = p[n], y = p[Nn + n], z = p[2 * Nn + n];
        float pn = __fadd_rn(__fadd_rn(__fmul_rn(x, x), __fmul_rn(y, y)),
                             __fmul_rn(z, z));
        g_xyz[(size_t)b * Nn + n] = make_float4(x, y, z, pn);
    }
    __syncthreads();

    float4 w;
    w.x = tile[4 * j + 0][i];
    w.y = tile[4 * j + 1][i];
    w.z = tile[4 * j + 2][i];
    w.w = tile[4 * j + 3][i];
    *(float4*)(d + (size_t)(n0 + i) * 128 + cbase + c0 + 4 * j) = w;
}

// ---------------------------------------------------------------------------
// Fused ball-query + gather + emit.  8 warps/CTA, one center per warp.
// 16 emit phases (center x {feat,temb} halves); k stays 32 per phase so
// every STG.128 store phase is one full 128B line.  smem ~19.5KB -> 8 CTA/SM.
// Staging: granule g (=cc>>2) of row k at word 4*((g ^ (k>>2)) & 15) + (cc&3)
// ---------------------------------------------------------------------------
__global__ void __launch_bounds__(256)
fused_kernel(const float* __restrict__ ctr,    // [B][3][M]
             float* __restrict__ out1,         // [B][67][M][K]
             float* __restrict__ out2)         // [B][64][M][K]
{
    __shared__ __align__(16) float  stg[2][KNN * SP2];   // 17.0KB dual-use
    __shared__ __align__(16) float4 spc[KNN];            // 512B
    __shared__ int    sidx[8][KNN];
    __shared__ float  scen[8][3];

    int t    = threadIdx.x;
    int warp = t >> 5;
    int lane = t & 31;
    int gw   = blockIdx.x * 8 + warp;
    int b    = gw >> 11;                  // same b for all 8 centers of a CTA
    int m    = gw & (Mm - 1);

    float cx = ctr[(size_t)b * 3 * Mm + m];
    float cy = ctr[(size_t)b * 3 * Mm + Mm + m];
    float cz = ctr[(size_t)b * 3 * Mm + 2 * Mm + m];
    float cn = __fadd_rn(__fadd_rn(__fmul_rn(cx, cx), __fmul_rn(cy, cy)),
                         __fmul_rn(cz, cz));
    if (lane == 0) {
        scen[warp][0] = cx; scen[warp][1] = cy; scen[warp][2] = cz;
    }

    const float4* xyz = g_xyz + (size_t)b * Nn;
    const float R2 = (float)(0.2 * 0.2);

    // ---- ordered first-K scan, double-buffered 512-point tiles ----
    float4* sbuf0 = (float4*)stg[0];
    float4* sbuf1 = (float4*)stg[1];

#pragma unroll
    for (int q = 0; q < 2; q++)                  // prefetch tile 0
        cp16(&sbuf0[t + q * 256], xyz + t + q * 256);
    CP_COMMIT();

    int count = 0;
    for (int tt = 0; tt < Nn / TILE; tt++) {
        float4* spts = (tt & 1) ? sbuf1 : sbuf0;
        float4* snxt = (tt & 1) ? sbuf0 : sbuf1;
        if (tt + 1 < Nn / TILE) {
#pragma unroll
            for (int q = 0; q < 2; q++)
                cp16(&snxt[t + q * 256],
                     xyz + (tt + 1) * TILE + t + q * 256);
        }
        CP_COMMIT();
        CP_WAIT1();                    // current tile's copies done (in-order)
        __syncthreads();

        if (count < KNN) {
            int t0 = tt * TILE;
            for (int g = 0; g < TILE && count < KNN; g += 128) {
                float4 p0 = spts[g + lane];
                float4 p1 = spts[g + 32 + lane];
                float4 p2 = spts[g + 64 + lane];
                float4 p3 = spts[g + 96 + lane];
#pragma unroll
                for (int i = 0; i < 4; i++) {
                    float4 p = (i == 0) ? p0 : (i == 1) ? p1
                             : (i == 2) ? p2 : p3;
                    float cross = fmaf(cz, p.z,
                                       fmaf(cy, p.y, __fmul_rn(cx, p.x)));
                    float d2 = __fsub_rn(__fadd_rn(cn, p.w),
                                         __fmul_rn(2.0f, cross));
                    bool valid = d2 < R2;
                    unsigned mask = __ballot_sync(0xffffffffu, valid);
                    if (valid) {
                        int pos = count + __popc(mask & ((1u << lane) - 1u));
                        if (pos < KNN)
                            sidx[warp][pos] = t0 + g + i * 32 + lane;
                    }
                    count += __popc(mask);
                }
            }
        }
        if (__syncthreads_and(count >= KNN)) break;
    }
    CP_WAIT0();                        // drain stale prefetches
    __syncwarp();

    // finalize index list (fill tail with first valid / 0)
    int cnt   = min(count, KNN);
    int first = (cnt > 0) ? sidx[warp][0] : 0;
    int n     = (lane < cnt) ? sidx[warp][lane] : first;
    __syncwarp();
    sidx[warp][lane] = n;
    __syncthreads();                   // sidx complete, buffers reusable

    // ---- emit: 16 phases = 8 centers x {feat(buf0), temb(buf1)} ----
    const size_t cs = (size_t)Mm * KNN;
    const float4* combB = (const float4*)g_comb + (size_t)b * Nn * 32;
    int t7 = lane & 7;         // k-quad 0..7
    int u  = lane >> 3;        // channel-within-quad 0..3
    int gB = lane & 15;        // granule within row-half
    int rH = lane >> 4;        // row-pair selector

#define STAGE_P(p)                                                           \
    {                                                                        \
        int ci_ = (p) >> 1, hf_ = (p) & 1;                                   \
        _Pragma("unroll")                                                    \
        for (int q = 0; q < 2; q++) {                                        \
            int r  = warp + 8 * (2 * q + rH);                                \
            int nk = sidx[ci_][r];                                           \
            cp16(&stg[hf_][r * SP2 + 4 * ((gB ^ (r >> 2)) & 15)],            \
                 combB + (size_t)nk * 32 + hf_ * 16 + gB);                   \
        }                                                                    \
        if (hf_ == 0 && lane < 4) {                                          \
            int r = warp + lane * 8;                                         \
            cp16(&spc[r], &g_xyz[(size_t)b * Nn + sidx[ci_][r]]);            \
        }                                                                    \
        CP_COMMIT();                                                         \
    }

    STAGE_P(0);
    for (int p = 0; p < 16; p++) {
        if (p < 15) STAGE_P(p + 1)
        else        CP_COMMIT();
        CP_WAIT1();                    // phase p's copies done (in-order)
        __syncthreads();

        int ci = p >> 1, hf = p & 1;
        int mi = (blockIdx.x * 8 + ci) & (Mm - 1);
        float* o1 = out1 + ((size_t)b * 67 * Mm + mi) * KNN;
        float* o2 = out2 + ((size_t)b * 64 * Mm + mi) * KNN;

        // 16 local channel-quads; warp w handles Qp = w, w+8.
#pragma unroll
        for (int q = 0; q < 2; q++) {
            int Qp = warp + 8 * q;             // local quad 0..15
            int sb = 4 * ((Qp ^ t7) & 15) + u;
            float4 o;
            o.x = stg[hf][(4 * t7 + 0) * SP2 + sb];
            o.y = stg[hf][(4 * t7 + 1) * SP2 + sb];
            o.z = stg[hf][(4 * t7 + 2) * SP2 + sb];
            o.w = stg[hf][(4 * t7 + 3) * SP2 + sb];
            int ccl = 4 * Qp + u;              // local channel 0..63
            float* dst = hf ? (o2 + (size_t)ccl * cs)
                            : (o1 + (size_t)(3 + ccl) * cs);
            __stcs((float4*)(dst + 4 * t7), o);
        }
        // coord channels 0..2 during feat phases: warps 0..2, one line each
        if (hf == 0 && warp < 3) {
            float4 pv = spc[lane];
            float comp = (warp == 0) ? pv.x : (warp == 1) ? pv.y : pv.z;
            __stcs(&o1[(size_t)warp * cs + lane],
                   __fsub_rn(comp, scen[ci][warp]));
        }
        __syncthreads();   // emit(p) done before its buffer is restaged
    }
#undef STAGE_P
}

// ---------------------------------------------------------------------------
extern "C" void kernel_launch(void* const* d_in, const int* in_sizes, int n_in,
                              void* d_out, int out_size)
{
    const float* pts  = (const float*)d_in[0];   // points_coords  [B,3,N]
    const float* ctr  = (const float*)d_in[1];   // centers_coords [B,3,M]
    const float* temb = (const float*)d_in[2];   // temb           [B,CT,N]
    const float* feat = (const float*)d_in[3];   // points_features[B,C,N]

    float* out1 = (float*)d_out;                                   // [B,67,M,K]
    float* out2 = out1 + (size_t)Bb * (3 + Cc) * Mm * KNN;         // [B,64,M,K]

    dim3 tb(8, 32);
    dim3 tg(Nn / 32, Cc / 32, Bb * 2);
    prep_kernel<<<tg, tb>>>(feat, temb, pts);

    fused_kernel<<<(Bb * Mm) / 8, 256>>>(ctr, out1, out2);
}